// round 1
// baseline (speedup 1.0000x reference)
#include <cuda_runtime.h>
#include <cstdint>
#include <cfloat>

// Problem constants
#define BB 32
#define DD 256
#define SS 2048
#define NN (BB*SS)   // 65536 rows
#define KK 4096      // codes

// Scratch (device globals: allocation-free per harness rules)
__device__ float g_cbT[(size_t)DD*KK];   // codebook transposed [d][k], 4MB
__device__ float g_enorm[KK];            // ||e_k||^2
__device__ float g_rx[NN];               // ||x_n||^2
__device__ int   g_idx[NN];              // argmin indices
__device__ float g_partial[65536];       // loss partial sums

// ---------------------------------------------------------------------------
// Transpose codebook [K][D] -> [D][K] for coalesced GEMM loads
// ---------------------------------------------------------------------------
__global__ void k_transpose(const float* __restrict__ cb) {
    __shared__ float tile[32][33];
    int k0 = blockIdx.x * 32, d0 = blockIdx.y * 32;
    int tx = threadIdx.x, ty = threadIdx.y;
    #pragma unroll
    for (int i = ty; i < 32; i += 8)
        tile[i][tx] = cb[(size_t)(k0 + i) * DD + d0 + tx];
    __syncthreads();
    #pragma unroll
    for (int i = ty; i < 32; i += 8)
        g_cbT[(size_t)(d0 + i) * KK + k0 + tx] = tile[tx][i];
}

// ---------------------------------------------------------------------------
// ||e_k||^2 : sequential fp32, product rounded then added (match x**2 then sum)
// ---------------------------------------------------------------------------
__global__ void k_enorm(const float* __restrict__ cb) {
    int k = blockIdx.x * blockDim.x + threadIdx.x;
    const float* p = cb + (size_t)k * DD;
    float acc = 0.f;
    for (int d = 0; d < DD; d++) {
        float v = p[d];
        acc = __fadd_rn(acc, __fmul_rn(v, v));
    }
    g_enorm[k] = acc;
}

// ---------------------------------------------------------------------------
// ||x_n||^2 : row n = (b, s); element (b, d, s) at stride S. Coalesced across n.
// ---------------------------------------------------------------------------
__global__ void k_rx(const float* __restrict__ x) {
    int n = blockIdx.x * blockDim.x + threadIdx.x;
    int b = n >> 11, s = n & 2047;
    const float* p = x + (size_t)b * DD * SS + s;
    float acc = 0.f;
    for (int d = 0; d < DD; d++) {
        float v = p[(size_t)d * SS];
        acc = __fadd_rn(acc, __fmul_rn(v, v));
    }
    g_rx[n] = acc;
}

// ---------------------------------------------------------------------------
// Fused SGEMM + argmin.
// Block: 256 threads. Tile: 128 rows x 128 codes, D in 16-chunks.
// Warp layout: 8 warps as (warp_r = w&3 over 4 row-groups of 32,
//                          warp_c = w>>2 over 2 code-groups of 64).
// Lane: lr = lane>>3 (4 row-subgroups of 8), lc = lane&7 (8 code-subgroups of 8).
// -> X smem reads: 4 distinct float4 broadcast x8 (conflict-free)
// -> E smem reads: 8 distinct float4 broadcast x4 (conflict-free)
// Single __syncthreads per chunk via store-then-compute double buffering.
// ---------------------------------------------------------------------------
__global__ void __launch_bounds__(256, 2) k_argmin(const float* __restrict__ x) {
    __shared__ float Xs[2][16][128];
    __shared__ float Es[2][16][128];
    __shared__ float rx_s[128];

    const int t = threadIdx.x;
    const int n0 = blockIdx.x * 128;                 // 128 | 2048 -> same batch b
    const float* xbase = x + (size_t)(n0 >> 11) * DD * SS + (n0 & 2047);

    const int lane = t & 31, w = t >> 5;
    const int ri0 = (w & 3) * 32 + (lane >> 3) * 8;  // this thread's 8 rows
    const int cj0 = (w >> 2) * 64 + (lane & 7) * 8;  // this thread's 8 codes (within tile)
    const int slot = (w >> 2) * 8 + (lane & 7);      // 0..15 reduction slot per row

    const int rr = t & 127, hi = t >> 7;             // loader mapping

    if (t < 128) rx_s[t] = g_rx[n0 + t];

    float acc[8][8];
    #pragma unroll
    for (int i = 0; i < 8; i++)
        #pragma unroll
        for (int j = 0; j < 8; j++) acc[i][j] = 0.f;

    float bestD[8]; int bestI[8];
    #pragma unroll
    for (int i = 0; i < 8; i++) { bestD[i] = FLT_MAX; bestI[i] = 0x7fffffff; }

    float ldX[8], ldE[8];

    // Prologue: load iter 0, store to buf0, load iter 1
    {
        #pragma unroll
        for (int i = 0; i < 8; i++) {
            int dd = 2 * i + hi;
            ldX[i] = xbase[(size_t)dd * SS + rr];
            ldE[i] = g_cbT[(size_t)dd * KK + rr];
        }
        #pragma unroll
        for (int i = 0; i < 8; i++) {
            int dd = 2 * i + hi;
            Xs[0][dd][rr] = ldX[i];
            Es[0][dd][rr] = ldE[i];
        }
        // iter 1: dc=1, ct=0 -> d0=16, c0=0
        #pragma unroll
        for (int i = 0; i < 8; i++) {
            int dd = 2 * i + hi;
            ldX[i] = xbase[(size_t)(16 + dd) * SS + rr];
            ldE[i] = g_cbT[(size_t)(16 + dd) * KK + rr];
        }
    }
    __syncthreads();

    float rxv[8];
    #pragma unroll
    for (int i = 0; i < 8; i++) rxv[i] = rx_s[ri0 + i];

    int buf = 0;
    for (int iter = 0; iter < 512; iter++) {   // 32 code-tiles x 16 d-chunks
        // store data for iter+1 (loaded last iteration) into the other buffer
        if (iter + 1 < 512) {
            #pragma unroll
            for (int i = 0; i < 8; i++) {
                int dd = 2 * i + hi;
                Xs[buf ^ 1][dd][rr] = ldX[i];
                Es[buf ^ 1][dd][rr] = ldE[i];
            }
        }
        // prefetch iter+2 into registers
        if (iter + 2 < 512) {
            int it2 = iter + 2;
            int d0 = (it2 & 15) * 16;
            int c0 = (it2 >> 4) * 128;
            #pragma unroll
            for (int i = 0; i < 8; i++) {
                int dd = 2 * i + hi;
                ldX[i] = xbase[(size_t)(d0 + dd) * SS + rr];
                ldE[i] = g_cbT[(size_t)(d0 + dd) * KK + c0 + rr];
            }
        }
        // compute current buffer
        #pragma unroll
        for (int kk = 0; kk < 16; kk++) {
            float4 xa = *(const float4*)&Xs[buf][kk][ri0];
            float4 xb = *(const float4*)&Xs[buf][kk][ri0 + 4];
            float4 ea = *(const float4*)&Es[buf][kk][cj0];
            float4 eb = *(const float4*)&Es[buf][kk][cj0 + 4];
            float xr[8] = {xa.x, xa.y, xa.z, xa.w, xb.x, xb.y, xb.z, xb.w};
            float er[8] = {ea.x, ea.y, ea.z, ea.w, eb.x, eb.y, eb.z, eb.w};
            #pragma unroll
            for (int i = 0; i < 8; i++)
                #pragma unroll
                for (int j = 0; j < 8; j++)
                    acc[i][j] = fmaf(xr[i], er[j], acc[i][j]);
        }
        // end of a code tile: distances + running argmin, reset accumulators
        if ((iter & 15) == 15) {
            int c0 = (iter >> 4) * 128;
            #pragma unroll
            for (int j = 0; j < 8; j++) {
                int c = c0 + cj0 + j;
                float ce = __ldg(&g_enorm[c]);
                #pragma unroll
                for (int i = 0; i < 8; i++) {
                    // replicate reference rounding: fl(fl(rx + ce) - 2*G)
                    float dist = __fsub_rn(__fadd_rn(rxv[i], ce),
                                           __fmul_rn(2.0f, acc[i][j]));
                    if (dist < bestD[i]) { bestD[i] = dist; bestI[i] = c; }
                    acc[i][j] = 0.f;
                }
            }
        }
        __syncthreads();
        buf ^= 1;
    }

    // cross-thread argmin reduction (16 threads per row), tie -> lower index
    float* redD = (float*)Xs;   // reuse: 128*16 floats
    int*   redI = (int*)Es;
    #pragma unroll
    for (int i = 0; i < 8; i++) {
        redD[(ri0 + i) * 16 + slot] = bestD[i];
        redI[(ri0 + i) * 16 + slot] = bestI[i];
    }
    __syncthreads();
    if (t < 128) {
        float bd = redD[t * 16];
        int   bi = redI[t * 16];
        #pragma unroll
        for (int j = 1; j < 16; j++) {
            float d2 = redD[t * 16 + j];
            int   i2 = redI[t * 16 + j];
            if (d2 < bd || (d2 == bd && i2 < bi)) { bd = d2; bi = i2; }
        }
        g_idx[n0 + t] = bi;
    }
}

// ---------------------------------------------------------------------------
// Gather + transpose writer + per-block loss partial (deterministic tree)
// grid = (N/256, D); thread -> n, blockIdx.y -> d. Writes coalesced in s.
// ---------------------------------------------------------------------------
__global__ void k_out(const float* __restrict__ x, float* __restrict__ out) {
    int n = blockIdx.x * 256 + threadIdx.x;
    int d = blockIdx.y;
    int idx = g_idx[n];
    float q = g_cbT[(size_t)d * KK + idx];
    size_t addr = (size_t)(n >> 11) * DD * SS + (size_t)d * SS + (n & 2047);
    float xv = x[addr];
    out[addr] = q;                // quantized_st == quantized numerically
    float df = q - xv;

    __shared__ float sm[256];
    sm[threadIdx.x] = df * df;
    __syncthreads();
    #pragma unroll
    for (int s2 = 128; s2 > 0; s2 >>= 1) {
        if (threadIdx.x < s2) sm[threadIdx.x] += sm[threadIdx.x + s2];
        __syncthreads();
    }
    if (threadIdx.x == 0)
        g_partial[blockIdx.y * gridDim.x + blockIdx.x] = sm[0];
}

// ---------------------------------------------------------------------------
// Final loss: deterministic fixed-order reduction of 65536 partials (double)
// loss = (COMMITMENT_COST + 1) * mean((q - x)^2) = 1.25 * mse
// ---------------------------------------------------------------------------
__global__ void k_loss(float* __restrict__ out, int out_size) {
    __shared__ double sm[256];
    int t = threadIdx.x;
    double acc = 0.0;
    for (int j = 0; j < 256; j++)
        acc += (double)g_partial[t + 256 * j];
    sm[t] = acc;
    __syncthreads();
    #pragma unroll
    for (int s2 = 128; s2 > 0; s2 >>= 1) {
        if (t < s2) sm[t] += sm[t + s2];
        __syncthreads();
    }
    if (t == 0) {
        double mse = sm[0] / (double)((size_t)NN * DD);
        out[out_size - 1] = (float)(1.25 * mse);
    }
}

// ---------------------------------------------------------------------------
extern "C" void kernel_launch(void* const* d_in, const int* in_sizes, int n_in,
                              void* d_out, int out_size) {
    const float* x  = (const float*)d_in[0];   // [32, 256, 2048] fp32
    const float* cb = (const float*)d_in[1];   // [4096, 256] fp32
    float* out = (float*)d_out;

    k_transpose<<<dim3(KK / 32, DD / 32), dim3(32, 8)>>>(cb);
    k_enorm<<<KK / 256, 256>>>(cb);
    k_rx<<<NN / 256, 256>>>(x);
    k_argmin<<<NN / 128, 256>>>(x);
    k_out<<<dim3(NN / 256, DD), 256>>>(x, out);
    k_loss<<<1, 256>>>(out, out_size);
}

// round 3
// speedup vs baseline: 1.0412x; 1.0412x over previous
#include <cuda_runtime.h>
#include <cstdint>
#include <cfloat>

// Problem constants
#define BB 32
#define DD 256
#define SS 2048
#define NN (BB*SS)   // 65536 rows
#define KK 4096      // codes

// Scratch (device globals: allocation-free per harness rules)
__device__ float g_cbT[(size_t)DD*KK];   // codebook transposed [d][k], 4MB
__device__ float g_enorm[KK];            // ||e_k||^2
__device__ float g_rx[NN];               // ||x_n||^2
__device__ int   g_idx[NN];              // argmin indices
__device__ float g_partial[65536];       // loss partial sums

// ---------------- packed f32x2 helpers (Blackwell FFMA2, PTX-only) ----------
__device__ __forceinline__ uint64_t pk2(float lo, float hi) {
    uint64_t r;
    asm("mov.b64 %0, {%1, %2};" : "=l"(r) : "f"(lo), "f"(hi));
    return r;
}
__device__ __forceinline__ void unpk2(uint64_t v, float& lo, float& hi) {
    asm("mov.b64 {%0, %1}, %2;" : "=f"(lo), "=f"(hi) : "l"(v));
}
__device__ __forceinline__ void fma2(uint64_t& d, uint64_t a, uint64_t b) {
    asm("fma.rn.f32x2 %0, %1, %2, %3;" : "=l"(d) : "l"(a), "l"(b), "l"(d));
}

// ---------------------------------------------------------------------------
// Transpose codebook [K][D] -> [D][K] for coalesced GEMM loads
// ---------------------------------------------------------------------------
__global__ void k_transpose(const float* __restrict__ cb) {
    __shared__ float tile[32][33];
    int k0 = blockIdx.x * 32, d0 = blockIdx.y * 32;
    int tx = threadIdx.x, ty = threadIdx.y;
    #pragma unroll
    for (int i = ty; i < 32; i += 8)
        tile[i][tx] = cb[(size_t)(k0 + i) * DD + d0 + tx];
    __syncthreads();
    #pragma unroll
    for (int i = ty; i < 32; i += 8)
        g_cbT[(size_t)(d0 + i) * KK + k0 + tx] = tile[tx][i];
}

// ---------------------------------------------------------------------------
__global__ void k_enorm(const float* __restrict__ cb) {
    int k = blockIdx.x * blockDim.x + threadIdx.x;
    const float* p = cb + (size_t)k * DD;
    float acc = 0.f;
    for (int d = 0; d < DD; d++) {
        float v = p[d];
        acc = __fadd_rn(acc, __fmul_rn(v, v));
    }
    g_enorm[k] = acc;
}

// ---------------------------------------------------------------------------
__global__ void k_rx(const float* __restrict__ x) {
    int n = blockIdx.x * blockDim.x + threadIdx.x;
    int b = n >> 11, s = n & 2047;
    const float* p = x + (size_t)b * DD * SS + s;
    float acc = 0.f;
    for (int d = 0; d < DD; d++) {
        float v = p[(size_t)d * SS];
        acc = __fadd_rn(acc, __fmul_rn(v, v));
    }
    g_rx[n] = acc;
}

// ---------------------------------------------------------------------------
// Fused SGEMM + argmin with packed f32x2 FMA (FFMA2).
// Block: 256 threads. Tile: 128 rows x 128 codes, D in 16-chunks.
// Same layout/ordering as the passing R1 kernel; only the j-dimension is
// packed in pairs (identical per-lane fp32 FMA sequence).
// ---------------------------------------------------------------------------
__global__ void __launch_bounds__(256, 2) k_argmin(const float* __restrict__ x) {
    __shared__ float Xs[2][16][128];
    __shared__ float Es[2][16][128];
    __shared__ float rx_s[128];

    const int t = threadIdx.x;
    const int n0 = blockIdx.x * 128;
    const float* xbase = x + (size_t)(n0 >> 11) * DD * SS + (n0 & 2047);

    const int lane = t & 31, w = t >> 5;
    const int ri0 = (w & 3) * 32 + (lane >> 3) * 8;  // this thread's 8 rows
    const int cj0 = (w >> 2) * 64 + (lane & 7) * 8;  // this thread's 8 codes
    const int slot = (w >> 2) * 8 + (lane & 7);      // 0..15 reduction slot

    const int rr = t & 127, hi = t >> 7;

    if (t < 128) rx_s[t] = g_rx[n0 + t];

    uint64_t acc2[8][4];
    #pragma unroll
    for (int i = 0; i < 8; i++)
        #pragma unroll
        for (int j = 0; j < 4; j++) acc2[i][j] = 0ull;

    float bestD[8]; int bestI[8];
    #pragma unroll
    for (int i = 0; i < 8; i++) { bestD[i] = FLT_MAX; bestI[i] = 0x7fffffff; }

    float ldX[8], ldE[8];

    // Prologue: load iter 0, store to buf0, load iter 1
    {
        #pragma unroll
        for (int i = 0; i < 8; i++) {
            int dd = 2 * i + hi;
            ldX[i] = xbase[(size_t)dd * SS + rr];
            ldE[i] = g_cbT[(size_t)dd * KK + rr];
        }
        #pragma unroll
        for (int i = 0; i < 8; i++) {
            int dd = 2 * i + hi;
            Xs[0][dd][rr] = ldX[i];
            Es[0][dd][rr] = ldE[i];
        }
        #pragma unroll
        for (int i = 0; i < 8; i++) {
            int dd = 2 * i + hi;
            ldX[i] = xbase[(size_t)(16 + dd) * SS + rr];
            ldE[i] = g_cbT[(size_t)(16 + dd) * KK + rr];
        }
    }
    __syncthreads();

    float rxv[8];
    #pragma unroll
    for (int i = 0; i < 8; i++) rxv[i] = rx_s[ri0 + i];

    int buf = 0;
    for (int iter = 0; iter < 512; iter++) {   // 32 code-tiles x 16 d-chunks
        if (iter + 1 < 512) {
            #pragma unroll
            for (int i = 0; i < 8; i++) {
                int dd = 2 * i + hi;
                Xs[buf ^ 1][dd][rr] = ldX[i];
                Es[buf ^ 1][dd][rr] = ldE[i];
            }
        }
        if (iter + 2 < 512) {
            int it2 = iter + 2;
            int d0 = (it2 & 15) * 16;
            int c0 = (it2 >> 4) * 128;
            #pragma unroll
            for (int i = 0; i < 8; i++) {
                int dd = 2 * i + hi;
                ldX[i] = xbase[(size_t)(d0 + dd) * SS + rr];
                ldE[i] = g_cbT[(size_t)(d0 + dd) * KK + c0 + rr];
            }
        }
        // compute current buffer — FFMA2 microtile
        #pragma unroll
        for (int kk = 0; kk < 16; kk++) {
            float4 xa = *(const float4*)&Xs[buf][kk][ri0];
            float4 xb = *(const float4*)&Xs[buf][kk][ri0 + 4];
            float4 ea = *(const float4*)&Es[buf][kk][cj0];
            float4 eb = *(const float4*)&Es[buf][kk][cj0 + 4];
            uint64_t e2[4];
            e2[0] = pk2(ea.x, ea.y);
            e2[1] = pk2(ea.z, ea.w);
            e2[2] = pk2(eb.x, eb.y);
            e2[3] = pk2(eb.z, eb.w);
            float xr[8] = {xa.x, xa.y, xa.z, xa.w, xb.x, xb.y, xb.z, xb.w};
            #pragma unroll
            for (int i = 0; i < 8; i++) {
                uint64_t x2 = pk2(xr[i], xr[i]);
                #pragma unroll
                for (int j = 0; j < 4; j++)
                    fma2(acc2[i][j], x2, e2[j]);
            }
        }
        // end of a code tile: distances + running argmin, reset accumulators
        if ((iter & 15) == 15) {
            int c0 = (iter >> 4) * 128;
            #pragma unroll
            for (int j = 0; j < 4; j++) {
                int c = c0 + cj0 + 2 * j;
                float ce0 = __ldg(&g_enorm[c]);
                float ce1 = __ldg(&g_enorm[c + 1]);
                #pragma unroll
                for (int i = 0; i < 8; i++) {
                    float g0, g1;
                    unpk2(acc2[i][j], g0, g1);
                    float d0v = __fsub_rn(__fadd_rn(rxv[i], ce0),
                                          __fmul_rn(2.0f, g0));
                    float d1v = __fsub_rn(__fadd_rn(rxv[i], ce1),
                                          __fmul_rn(2.0f, g1));
                    if (d0v < bestD[i]) { bestD[i] = d0v; bestI[i] = c; }
                    if (d1v < bestD[i]) { bestD[i] = d1v; bestI[i] = c + 1; }
                    acc2[i][j] = 0ull;
                }
            }
        }
        __syncthreads();
        buf ^= 1;
    }

    // cross-thread argmin reduction (16 threads per row), tie -> lower index
    float* redD = (float*)Xs;
    int*   redI = (int*)Es;
    #pragma unroll
    for (int i = 0; i < 8; i++) {
        redD[(ri0 + i) * 16 + slot] = bestD[i];
        redI[(ri0 + i) * 16 + slot] = bestI[i];
    }
    __syncthreads();
    if (t < 128) {
        float bd = redD[t * 16];
        int   bi = redI[t * 16];
        #pragma unroll
        for (int j = 1; j < 16; j++) {
            float d2 = redD[t * 16 + j];
            int   i2 = redI[t * 16 + j];
            if (d2 < bd || (d2 == bd && i2 < bi)) { bd = d2; bi = i2; }
        }
        g_idx[n0 + t] = bi;
    }
}

// ---------------------------------------------------------------------------
__global__ void k_out(const float* __restrict__ x, float* __restrict__ out) {
    int n = blockIdx.x * 256 + threadIdx.x;
    int d = blockIdx.y;
    int idx = g_idx[n];
    float q = g_cbT[(size_t)d * KK + idx];
    size_t addr = (size_t)(n >> 11) * DD * SS + (size_t)d * SS + (n & 2047);
    float xv = x[addr];
    out[addr] = q;
    float df = q - xv;

    __shared__ float sm[256];
    sm[threadIdx.x] = df * df;
    __syncthreads();
    #pragma unroll
    for (int s2 = 128; s2 > 0; s2 >>= 1) {
        if (threadIdx.x < s2) sm[threadIdx.x] += sm[threadIdx.x + s2];
        __syncthreads();
    }
    if (threadIdx.x == 0)
        g_partial[blockIdx.y * gridDim.x + blockIdx.x] = sm[0];
}

// ---------------------------------------------------------------------------
__global__ void k_loss(float* __restrict__ out, int out_size) {
    __shared__ double sm[256];
    int t = threadIdx.x;
    double acc = 0.0;
    for (int j = 0; j < 256; j++)
        acc += (double)g_partial[t + 256 * j];
    sm[t] = acc;
    __syncthreads();
    #pragma unroll
    for (int s2 = 128; s2 > 0; s2 >>= 1) {
        if (t < s2) sm[t] += sm[t + s2];
        __syncthreads();
    }
    if (t == 0) {
        double mse = sm[0] / (double)((size_t)NN * DD);
        out[out_size - 1] = (float)(1.25 * mse);
    }
}

// ---------------------------------------------------------------------------
extern "C" void kernel_launch(void* const* d_in, const int* in_sizes, int n_in,
                              void* d_out, int out_size) {
    const float* x  = (const float*)d_in[0];   // [32, 256, 2048] fp32
    const float* cb = (const float*)d_in[1];   // [4096, 256] fp32
    float* out = (float*)d_out;

    k_transpose<<<dim3(KK / 32, DD / 32), dim3(32, 8)>>>(cb);
    k_enorm<<<KK / 256, 256>>>(cb);
    k_rx<<<NN / 256, 256>>>(x);
    k_argmin<<<NN / 128, 256>>>(x);
    k_out<<<dim3(NN / 256, DD), 256>>>(x, out);
    k_loss<<<1, 256>>>(out, out_size);
}

// round 5
// speedup vs baseline: 3.4186x; 3.2833x over previous
#include <cuda_runtime.h>
#include <cuda_bf16.h>
#include <cstdint>
#include <cfloat>

#define BB 32
#define DD 256
#define SS 2048
#define NN (BB*SS)   // 65536 rows
#define KK 4096      // codes

#define MARGIN 8e-4f

// ---------------- device globals (no allocs allowed) ----------------
__device__ float g_cbT[(size_t)DD*KK];        // codebook transposed [d][k] (k_out)
__device__ float g_enorm[KK];                 // ||e_k||^2
__device__ float g_rx[NN];                    // ||x_n||^2
__device__ int   g_idx[NN];                   // argmin indices
__device__ float g_partial[65536];            // loss partials
__device__ __nv_bfloat16 g_ebf[(size_t)KK*DD];   // bf16 codebook [c][d]
__device__ __nv_bfloat16 g_sd[(size_t)NN*KK];    // screen scores s' (bf16), 512MB

// ---------------- helpers ----------------
__device__ __forceinline__ uint32_t smem_u32(const void* p) {
    uint32_t a;
    asm("{ .reg .u64 t; cvta.to.shared.u64 t, %1; cvt.u32.u64 %0, t; }" : "=r"(a) : "l"(p));
    return a;
}
__device__ __forceinline__ void ldm_x4(uint32_t (&r)[4], uint32_t addr) {
    asm volatile("ldmatrix.sync.aligned.m8n8.x4.shared.b16 {%0,%1,%2,%3}, [%4];"
        : "=r"(r[0]), "=r"(r[1]), "=r"(r[2]), "=r"(r[3]) : "r"(addr));
}
__device__ __forceinline__ void hmma(float (&d)[4], const uint32_t (&a)[4],
                                     uint32_t b0, uint32_t b1) {
    asm volatile("mma.sync.aligned.m16n8k16.row.col.f32.bf16.bf16.f32 "
        "{%0,%1,%2,%3}, {%4,%5,%6,%7}, {%8,%9}, {%0,%1,%2,%3};"
        : "+f"(d[0]), "+f"(d[1]), "+f"(d[2]), "+f"(d[3])
        : "r"(a[0]), "r"(a[1]), "r"(a[2]), "r"(a[3]), "r"(b0), "r"(b1));
}

// ---------------- prep kernels ----------------
__global__ void k_transpose(const float* __restrict__ cb) {
    __shared__ float tile[32][33];
    int k0 = blockIdx.x * 32, d0 = blockIdx.y * 32;
    int tx = threadIdx.x, ty = threadIdx.y;
    for (int i = ty; i < 32; i += 8)
        tile[i][tx] = cb[(size_t)(k0 + i) * DD + d0 + tx];
    __syncthreads();
    for (int i = ty; i < 32; i += 8)
        g_cbT[(size_t)(d0 + i) * KK + k0 + tx] = tile[tx][i];
}

__global__ void k_enorm(const float* __restrict__ cb) {
    int k = blockIdx.x * blockDim.x + threadIdx.x;
    const float* p = cb + (size_t)k * DD;
    float acc = 0.f;
    for (int d = 0; d < DD; d++) { float v = p[d]; acc = __fadd_rn(acc, __fmul_rn(v, v)); }
    g_enorm[k] = acc;
}

__global__ void k_rx(const float* __restrict__ x) {
    int n = blockIdx.x * blockDim.x + threadIdx.x;
    const float* p = x + (size_t)(n >> 11) * DD * SS + (n & 2047);
    float acc = 0.f;
    for (int d = 0; d < DD; d++) { float v = p[(size_t)d * SS]; acc = __fadd_rn(acc, __fmul_rn(v, v)); }
    g_rx[n] = acc;
}

__global__ void k_ebf(const float* __restrict__ cb) {
    size_t i = (size_t)blockIdx.x * 256 + threadIdx.x;
    g_ebf[i] = __float2bfloat16(cb[i]);
}

// ---------------- K1: bf16 HMMA screen ----------------
// CTA: 128 rows x all 4096 codes (32 tiles of 128). Warps 8: wr=w&3 (32 rows),
// wc=w>>2 (64 codes). Xh resident [128][264 pad] bf16; E chunks [128c][40 pad] bf16 x2.
#define XH_STRIDE 264
#define E_STRIDE  40
#define SM_XH     0
#define SM_E0     67584
#define SM_E1     77824
#define SM_K1_TOT 88064

__global__ void __launch_bounds__(256, 2) k_screen(const float* __restrict__ x) {
    extern __shared__ char sm[];
    const uint32_t sb = smem_u32(sm);
    const int t = threadIdx.x, lane = t & 31, w = t >> 5;
    const int n0 = blockIdx.x * 128;
    const float* xbase = x + (size_t)(n0 >> 11) * DD * SS + (n0 & 2047);

    // build Xh (bf16 rn), coalesced global reads
    for (int i = t; i < 128 * 256; i += 256) {
        int d = i >> 7, r = i & 127;
        float v = __ldg(xbase + (size_t)d * SS + r);
        *(__nv_bfloat16*)(sm + SM_XH + (r * XH_STRIDE + d) * 2) = __float2bfloat16(v);
    }

    const int wr = w & 3, wc = w >> 2;
    const int RB = wr * 32, CB = wc * 64;

    float acc[2][8][4];
    #pragma unroll
    for (int mt = 0; mt < 2; mt++)
        #pragma unroll
        for (int nt = 0; nt < 8; nt++)
            #pragma unroll
            for (int i = 0; i < 4; i++) acc[mt][nt][i] = 0.f;

    // E chunk loader indices: thread covers row c=t>>1, half=t&1 (16 bf16 = 32B)
    const int lc = t >> 1, lh = t & 1;
    uint4 st0, st1;
    {   // prefetch chunk 0 (tile 0, kc 0)
        const char* src = (const char*)(g_ebf + (size_t)lc * 256 + lh * 16);
        st0 = __ldg((const uint4*)src);
        st1 = __ldg((const uint4*)(src + 16));
        char* dst = sm + SM_E0 + (lc * E_STRIDE + lh * 16) * 2;
        *(uint4*)dst = st0; *(uint4*)(dst + 16) = st1;
    }
    __syncthreads();

    // ldmatrix address lanes (constant parts)
    const int a_row = (lane & 7) + ((lane >> 3) & 1) * 8;   // row within 16
    const int a_kh  = ((lane >> 4) & 1) * 8;                // k half
    const int b_row = (lane & 7) + ((lane >> 4) & 1) * 8;   // n within 16
    const int b_kh  = ((lane >> 3) & 1) * 8;                // k half

    int cur = 0;
    for (int ci = 0; ci < 256; ci++) {       // 32 tiles x 8 k-chunks(32)
        const int tt = ci >> 3, kc = ci & 7;
        // prefetch next chunk into regs
        if (ci + 1 < 256) {
            int t2 = (ci + 1) >> 3, k2 = (ci + 1) & 7;
            const char* src = (const char*)(g_ebf + ((size_t)t2 * 128 + lc) * 256 + k2 * 32 + lh * 16);
            st0 = __ldg((const uint4*)src);
            st1 = __ldg((const uint4*)(src + 16));
        }
        // compute current chunk: 2 k-steps of 16
        const uint32_t ebase = sb + (cur ? SM_E1 : SM_E0);
        #pragma unroll
        for (int ks = 0; ks < 2; ks++) {
            const int k0 = kc * 32 + ks * 16;     // global k for A
            uint32_t a[2][4];
            #pragma unroll
            for (int mt = 0; mt < 2; mt++)
                ldm_x4(a[mt], sb + SM_XH +
                    ((RB + mt * 16 + a_row) * XH_STRIDE + k0 + a_kh) * 2);
            // B: non-trans ldmatrix — E tile is [n][k] with k contiguous,
            // which IS col-major KxN; fragment = thread holds k-pair at its n.
            uint32_t bf[4][4];
            #pragma unroll
            for (int p = 0; p < 4; p++)
                ldm_x4(bf[p], ebase +
                    ((CB + p * 16 + b_row) * E_STRIDE + ks * 16 + b_kh) * 2);
            #pragma unroll
            for (int mt = 0; mt < 2; mt++)
                #pragma unroll
                for (int nt = 0; nt < 8; nt++)
                    hmma(acc[mt][nt], a[mt], bf[nt >> 1][(nt & 1) * 2],
                         bf[nt >> 1][(nt & 1) * 2 + 1]);
        }
        // store next chunk
        if (ci + 1 < 256) {
            char* dst = sm + (cur ? SM_E0 : SM_E1) + (lc * E_STRIDE + lh * 16) * 2;
            *(uint4*)dst = st0; *(uint4*)(dst + 16) = st1;
        }
        // tile epilogue: s' = ce - 2g, bf16-pack, store; zero acc
        if (kc == 7) {
            const int tb = tt * 128;
            #pragma unroll
            for (int mt = 0; mt < 2; mt++) {
                const int gr = RB + mt * 16 + (lane >> 2);
                #pragma unroll
                for (int nt = 0; nt < 8; nt++) {
                    const int gcol = tb + CB + nt * 8 + (lane & 3) * 2;
                    float2 ce = __ldg((const float2*)&g_enorm[gcol]);
                    float s0 = ce.x - 2.f * acc[mt][nt][0];
                    float s1 = ce.y - 2.f * acc[mt][nt][1];
                    float s2 = ce.x - 2.f * acc[mt][nt][2];
                    float s3 = ce.y - 2.f * acc[mt][nt][3];
                    __nv_bfloat162 p0 = __floats2bfloat162_rn(s0, s1);
                    __nv_bfloat162 p1 = __floats2bfloat162_rn(s2, s3);
                    uint32_t* sd32 = (uint32_t*)g_sd;
                    sd32[(size_t)(n0 + gr) * 2048 + (gcol >> 1)]     = *(uint32_t*)&p0;
                    sd32[(size_t)(n0 + gr + 8) * 2048 + (gcol >> 1)] = *(uint32_t*)&p1;
                    acc[mt][nt][0] = acc[mt][nt][1] = acc[mt][nt][2] = acc[mt][nt][3] = 0.f;
                }
            }
        }
        __syncthreads();
        cur ^= 1;
    }
}

// ---------------- K2: scan + exact rescue (warp per row) ----------------
__global__ void __launch_bounds__(256) k_pick(const float* __restrict__ x,
                                              const float* __restrict__ cb) {
    const int gw = (blockIdx.x * 256 + threadIdx.x) >> 5;   // row id
    const int lane = threadIdx.x & 31;
    const int n = gw;
    const float* xp = x + (size_t)(n >> 11) * DD * SS + (n & 2047);

    // x row in regs (lane-split over d)
    float xr[8];
    #pragma unroll
    for (int j = 0; j < 8; j++)
        xr[j] = __ldg(xp + (size_t)(lane + 32 * j) * SS);

    const uint32_t* sp = (const uint32_t*)(g_sd + (size_t)n * KK);

    // pass 1: min of screen scores
    float mn = FLT_MAX;
    for (int it = 0; it < 64; it++) {
        uint32_t u = __ldg(sp + it * 32 + lane);
        __nv_bfloat162 p = *(__nv_bfloat162*)&u;
        mn = fminf(mn, fminf(__bfloat162float(p.x), __bfloat162float(p.y)));
    }
    #pragma unroll
    for (int o = 16; o > 0; o >>= 1)
        mn = fminf(mn, __shfl_xor_sync(0xFFFFFFFFu, mn, o));
    const float thresh = mn + MARGIN;
    const float rxv = __ldg(&g_rx[n]);

    float bd = FLT_MAX; int bi = 0x7fffffff;

    // pass 2: candidates in ascending code order, exact fp32 rescore
    for (int it = 0; it < 64; it++) {
        uint32_t u = __ldg(sp + it * 32 + lane);
        __nv_bfloat162 p = *(__nv_bfloat162*)&u;
        unsigned m0 = __ballot_sync(0xFFFFFFFFu, __bfloat162float(p.x) <= thresh);
        unsigned m1 = __ballot_sync(0xFFFFFFFFu, __bfloat162float(p.y) <= thresh);
        unsigned mm = m0 | m1;
        while (mm) {
            int l = __ffs(mm) - 1; mm &= mm - 1;
            #pragma unroll
            for (int half = 0; half < 2; half++) {
                if (!((half ? m1 : m0) >> l & 1)) continue;
                int c = it * 64 + 2 * l + half;
                const float* ep = cb + (size_t)c * DD;
                float pa = 0.f;
                #pragma unroll
                for (int j = 0; j < 8; j++)
                    pa = fmaf(xr[j], __ldg(ep + lane + 32 * j), pa);
                #pragma unroll
                for (int o = 16; o > 0; o >>= 1)
                    pa += __shfl_down_sync(0xFFFFFFFFu, pa, o);
                pa = __shfl_sync(0xFFFFFFFFu, pa, 0);
                float ce = __ldg(&g_enorm[c]);
                float dist = __fsub_rn(__fadd_rn(rxv, ce), __fmul_rn(2.0f, pa));
                if (dist < bd || (dist == bd && c < bi)) { bd = dist; bi = c; }
            }
        }
    }
    if (lane == 0) g_idx[n] = bi;
}

// ---------------- output + loss ----------------
__global__ void k_out(const float* __restrict__ x, float* __restrict__ out) {
    int n = blockIdx.x * 256 + threadIdx.x;
    int d = blockIdx.y;
    int idx = g_idx[n];
    float q = g_cbT[(size_t)d * KK + idx];
    size_t addr = (size_t)(n >> 11) * DD * SS + (size_t)d * SS + (n & 2047);
    float xv = x[addr];
    out[addr] = q;
    float df = q - xv;
    __shared__ float smr[256];
    smr[threadIdx.x] = df * df;
    __syncthreads();
    #pragma unroll
    for (int s2 = 128; s2 > 0; s2 >>= 1) {
        if (threadIdx.x < s2) smr[threadIdx.x] += smr[threadIdx.x + s2];
        __syncthreads();
    }
    if (threadIdx.x == 0) g_partial[blockIdx.y * gridDim.x + blockIdx.x] = smr[0];
}

__global__ void k_loss(float* __restrict__ out, int out_size) {
    __shared__ double smr[256];
    int t = threadIdx.x;
    double acc = 0.0;
    for (int j = 0; j < 256; j++) acc += (double)g_partial[t + 256 * j];
    smr[t] = acc;
    __syncthreads();
    #pragma unroll
    for (int s2 = 128; s2 > 0; s2 >>= 1) {
        if (t < s2) smr[t] += smr[t + s2];
        __syncthreads();
    }
    if (t == 0) {
        double mse = smr[0] / (double)((size_t)NN * DD);
        out[out_size - 1] = (float)(1.25 * mse);
    }
}

// ---------------- launch ----------------
extern "C" void kernel_launch(void* const* d_in, const int* in_sizes, int n_in,
                              void* d_out, int out_size) {
    const float* x  = (const float*)d_in[0];
    const float* cb = (const float*)d_in[1];
    float* out = (float*)d_out;

    static bool attr_set = false;
    if (!attr_set) {
        cudaFuncSetAttribute(k_screen, cudaFuncAttributeMaxDynamicSharedMemorySize, SM_K1_TOT);
        attr_set = true;
    }

    k_transpose<<<dim3(KK / 32, DD / 32), dim3(32, 8)>>>(cb);
    k_enorm<<<KK / 256, 256>>>(cb);
    k_rx<<<NN / 256, 256>>>(x);
    k_ebf<<<(KK * DD) / 256, 256>>>(cb);
    k_screen<<<NN / 128, 256, SM_K1_TOT>>>(x);
    k_pick<<<NN / 8, 256>>>(x, cb);
    k_out<<<dim3(NN / 256, DD), 256>>>(x, out);
    k_loss<<<1, 256>>>(out, out_size);
}

// round 6
// speedup vs baseline: 3.8885x; 1.1374x over previous
#include <cuda_runtime.h>
#include <cuda_bf16.h>
#include <cstdint>
#include <cfloat>

#define BB 32
#define DD 256
#define SS 2048
#define NN (BB*SS)   // 65536 rows
#define KK 4096      // codes

#define MARGIN 8e-4f
#define CAP 32

// ---------------- device globals (no allocs allowed) ----------------
__device__ float g_cbT[(size_t)DD*KK];        // codebook transposed [d][k] (k_out)
__device__ float g_enorm[KK];                 // ||e_k||^2
__device__ float g_rx[NN];                    // ||x_n||^2
__device__ int   g_idx[NN];                   // argmin indices
__device__ float g_partial[65536];            // loss partials
__device__ __nv_bfloat16 g_ebf[(size_t)KK*DD];   // bf16 codebook [c][d]
__device__ int   g_ccnt[NN];                  // candidate counts
__device__ int   g_cand[(size_t)NN*CAP];      // candidate code ids (8MB)

// ---------------- helpers ----------------
__device__ __forceinline__ uint32_t smem_u32(const void* p) {
    uint32_t a;
    asm("{ .reg .u64 t; cvta.to.shared.u64 t, %1; cvt.u32.u64 %0, t; }" : "=r"(a) : "l"(p));
    return a;
}
__device__ __forceinline__ void ldm_x4(uint32_t (&r)[4], uint32_t addr) {
    asm volatile("ldmatrix.sync.aligned.m8n8.x4.shared.b16 {%0,%1,%2,%3}, [%4];"
        : "=r"(r[0]), "=r"(r[1]), "=r"(r[2]), "=r"(r[3]) : "r"(addr));
}
__device__ __forceinline__ void hmma(float (&d)[4], const uint32_t (&a)[4],
                                     uint32_t b0, uint32_t b1) {
    asm volatile("mma.sync.aligned.m16n8k16.row.col.f32.bf16.bf16.f32 "
        "{%0,%1,%2,%3}, {%4,%5,%6,%7}, {%8,%9}, {%0,%1,%2,%3};"
        : "+f"(d[0]), "+f"(d[1]), "+f"(d[2]), "+f"(d[3])
        : "r"(a[0]), "r"(a[1]), "r"(a[2]), "r"(a[3]), "r"(b0), "r"(b1));
}
// monotone float<->uint encoding for atomicMin over floats (any sign)
__device__ __forceinline__ unsigned fenc(float f) {
    int b = __float_as_int(f);
    return b >= 0 ? ((unsigned)b | 0x80000000u) : ~(unsigned)b;
}
__device__ __forceinline__ float fdec(unsigned u) {
    int b = (u & 0x80000000u) ? (int)(u ^ 0x80000000u) : ~(int)u;
    return __int_as_float(b);
}

// ---------------- prep kernels ----------------
__global__ void k_transpose(const float* __restrict__ cb) {
    __shared__ float tile[32][33];
    int k0 = blockIdx.x * 32, d0 = blockIdx.y * 32;
    int tx = threadIdx.x, ty = threadIdx.y;
    for (int i = ty; i < 32; i += 8)
        tile[i][tx] = cb[(size_t)(k0 + i) * DD + d0 + tx];
    __syncthreads();
    for (int i = ty; i < 32; i += 8)
        g_cbT[(size_t)(d0 + i) * KK + k0 + tx] = tile[tx][i];
}

__global__ void k_enorm(const float* __restrict__ cb) {
    int k = blockIdx.x * blockDim.x + threadIdx.x;
    const float* p = cb + (size_t)k * DD;
    float acc = 0.f;
    for (int d = 0; d < DD; d++) { float v = p[d]; acc = __fadd_rn(acc, __fmul_rn(v, v)); }
    g_enorm[k] = acc;
}

__global__ void k_rx(const float* __restrict__ x) {
    int n = blockIdx.x * blockDim.x + threadIdx.x;
    const float* p = x + (size_t)(n >> 11) * DD * SS + (n & 2047);
    float acc = 0.f;
    for (int d = 0; d < DD; d++) { float v = p[(size_t)d * SS]; acc = __fadd_rn(acc, __fmul_rn(v, v)); }
    g_rx[n] = acc;
    g_ccnt[n] = 0;
}

__global__ void k_ebf(const float* __restrict__ cb) {
    size_t i = (size_t)blockIdx.x * 256 + threadIdx.x;
    g_ebf[i] = __float2bfloat16(cb[i]);
}

// ---------------- K1: bf16 HMMA screen + fused candidate capture ----------
#define XH_STRIDE 264
#define E_STRIDE  40
#define SM_XH     0
#define SM_E0     67584
#define SM_E1     77824
#define SM_K1_TOT 88064

__global__ void __launch_bounds__(256, 2) k_screen(const float* __restrict__ x) {
    extern __shared__ char sm[];
    __shared__ unsigned rmin[128];     // encoded running row-min
    const uint32_t sb = smem_u32(sm);
    const int t = threadIdx.x, lane = t & 31, w = t >> 5;
    const int n0 = blockIdx.x * 128;
    const float* xbase = x + (size_t)(n0 >> 11) * DD * SS + (n0 & 2047);

    if (t < 128) rmin[t] = 0xFFFFFFFFu;

    // build Xh (bf16 rn), coalesced global reads
    for (int i = t; i < 128 * 256; i += 256) {
        int d = i >> 7, r = i & 127;
        float v = __ldg(xbase + (size_t)d * SS + r);
        *(__nv_bfloat16*)(sm + SM_XH + (r * XH_STRIDE + d) * 2) = __float2bfloat16(v);
    }

    const int wr = w & 3, wc = w >> 2;
    const int RB = wr * 32, CB = wc * 64;

    float acc[2][8][4];
    #pragma unroll
    for (int mt = 0; mt < 2; mt++)
        #pragma unroll
        for (int nt = 0; nt < 8; nt++)
            #pragma unroll
            for (int i = 0; i < 4; i++) acc[mt][nt][i] = 0.f;

    const int lc = t >> 1, lh = t & 1;
    uint4 st0, st1;
    {   // prefetch chunk 0
        const char* src = (const char*)(g_ebf + (size_t)lc * 256 + lh * 16);
        st0 = __ldg((const uint4*)src);
        st1 = __ldg((const uint4*)(src + 16));
        char* dst = sm + SM_E0 + (lc * E_STRIDE + lh * 16) * 2;
        *(uint4*)dst = st0; *(uint4*)(dst + 16) = st1;
    }
    __syncthreads();

    const int a_row = (lane & 7) + ((lane >> 3) & 1) * 8;
    const int a_kh  = ((lane >> 4) & 1) * 8;
    const int b_row = (lane & 7) + ((lane >> 4) & 1) * 8;
    const int b_kh  = ((lane >> 3) & 1) * 8;

    int cur = 0;
    for (int ci = 0; ci < 256; ci++) {       // 32 tiles x 8 k-chunks(32)
        const int tt = ci >> 3, kc = ci & 7;
        if (ci + 1 < 256) {
            int t2 = (ci + 1) >> 3, k2 = (ci + 1) & 7;
            const char* src = (const char*)(g_ebf + ((size_t)t2 * 128 + lc) * 256 + k2 * 32 + lh * 16);
            st0 = __ldg((const uint4*)src);
            st1 = __ldg((const uint4*)(src + 16));
        }
        const uint32_t ebase = sb + (cur ? SM_E1 : SM_E0);
        #pragma unroll
        for (int ks = 0; ks < 2; ks++) {
            const int k0 = kc * 32 + ks * 16;
            uint32_t a[2][4];
            #pragma unroll
            for (int mt = 0; mt < 2; mt++)
                ldm_x4(a[mt], sb + SM_XH +
                    ((RB + mt * 16 + a_row) * XH_STRIDE + k0 + a_kh) * 2);
            uint32_t bf[4][4];
            #pragma unroll
            for (int p = 0; p < 4; p++)
                ldm_x4(bf[p], ebase +
                    ((CB + p * 16 + b_row) * E_STRIDE + ks * 16 + b_kh) * 2);
            #pragma unroll
            for (int mt = 0; mt < 2; mt++)
                #pragma unroll
                for (int nt = 0; nt < 8; nt++)
                    hmma(acc[mt][nt], a[mt], bf[nt >> 1][(nt & 1) * 2],
                         bf[nt >> 1][(nt & 1) * 2 + 1]);
        }
        if (ci + 1 < 256) {
            char* dst = sm + (cur ? SM_E0 : SM_E1) + (lc * E_STRIDE + lh * 16) * 2;
            *(uint4*)dst = st0; *(uint4*)(dst + 16) = st1;
        }
        // tile epilogue: running row-min update, then candidate capture
        if (kc == 7) {
            const int tb = tt * 128;
            // phase 1: per-thread min per row, atomicMin into smem
            #pragma unroll
            for (int mt = 0; mt < 2; mt++) {
                float mn01 = FLT_MAX, mn23 = FLT_MAX;
                #pragma unroll
                for (int nt = 0; nt < 8; nt++) {
                    const int gcol = tb + CB + nt * 8 + (lane & 3) * 2;
                    float2 ce = __ldg((const float2*)&g_enorm[gcol]);
                    mn01 = fminf(mn01, fminf(ce.x - 2.f * acc[mt][nt][0],
                                             ce.y - 2.f * acc[mt][nt][1]));
                    mn23 = fminf(mn23, fminf(ce.x - 2.f * acc[mt][nt][2],
                                             ce.y - 2.f * acc[mt][nt][3]));
                }
                const int r0 = RB + mt * 16 + (lane >> 2);
                atomicMin(&rmin[r0], fenc(mn01));
                atomicMin(&rmin[r0 + 8], fenc(mn23));
            }
            __syncthreads();
            // phase 2: append candidates under rowmin+MARGIN, zero acc
            #pragma unroll
            for (int mt = 0; mt < 2; mt++) {
                const int r0 = RB + mt * 16 + (lane >> 2);
                const float th0 = fdec(rmin[r0]) + MARGIN;
                const float th1 = fdec(rmin[r0 + 8]) + MARGIN;
                #pragma unroll
                for (int nt = 0; nt < 8; nt++) {
                    const int gcol = tb + CB + nt * 8 + (lane & 3) * 2;
                    float2 ce = __ldg((const float2*)&g_enorm[gcol]);
                    float s0 = ce.x - 2.f * acc[mt][nt][0];
                    float s1 = ce.y - 2.f * acc[mt][nt][1];
                    float s2 = ce.x - 2.f * acc[mt][nt][2];
                    float s3 = ce.y - 2.f * acc[mt][nt][3];
                    if (s0 <= th0) {
                        int p = atomicAdd(&g_ccnt[n0 + r0], 1);
                        if (p < CAP) g_cand[(size_t)(n0 + r0) * CAP + p] = gcol;
                    }
                    if (s1 <= th0) {
                        int p = atomicAdd(&g_ccnt[n0 + r0], 1);
                        if (p < CAP) g_cand[(size_t)(n0 + r0) * CAP + p] = gcol + 1;
                    }
                    if (s2 <= th1) {
                        int p = atomicAdd(&g_ccnt[n0 + r0 + 8], 1);
                        if (p < CAP) g_cand[(size_t)(n0 + r0 + 8) * CAP + p] = gcol;
                    }
                    if (s3 <= th1) {
                        int p = atomicAdd(&g_ccnt[n0 + r0 + 8], 1);
                        if (p < CAP) g_cand[(size_t)(n0 + r0 + 8) * CAP + p] = gcol + 1;
                    }
                    acc[mt][nt][0] = acc[mt][nt][1] = acc[mt][nt][2] = acc[mt][nt][3] = 0.f;
                }
            }
        }
        __syncthreads();
        cur ^= 1;
    }
}

// ---------------- K2: exact rescue over candidates (warp per row) --------
__global__ void __launch_bounds__(256) k_rescue(const float* __restrict__ x,
                                                const float* __restrict__ cb) {
    const int n = (blockIdx.x * 256 + threadIdx.x) >> 5;
    const int lane = threadIdx.x & 31;
    const float* xp = x + (size_t)(n >> 11) * DD * SS + (n & 2047);

    float xr[8];
    #pragma unroll
    for (int j = 0; j < 8; j++)
        xr[j] = __ldg(xp + (size_t)(lane + 32 * j) * SS);

    int cnt = __ldg(&g_ccnt[n]);
    if (cnt > CAP) cnt = CAP;
    const float rxv = __ldg(&g_rx[n]);

    float bd = FLT_MAX; int bi = 0x7fffffff;
    for (int i = 0; i < cnt; i++) {
        int c = __ldg(&g_cand[(size_t)n * CAP + i]);
        const float* ep = cb + (size_t)c * DD;
        float pa = 0.f;
        #pragma unroll
        for (int j = 0; j < 8; j++)
            pa = fmaf(xr[j], __ldg(ep + lane + 32 * j), pa);
        #pragma unroll
        for (int o = 16; o > 0; o >>= 1)
            pa += __shfl_down_sync(0xFFFFFFFFu, pa, o);
        pa = __shfl_sync(0xFFFFFFFFu, pa, 0);
        float ce = __ldg(&g_enorm[c]);
        float dist = __fsub_rn(__fadd_rn(rxv, ce), __fmul_rn(2.0f, pa));
        if (dist < bd || (dist == bd && c < bi)) { bd = dist; bi = c; }
    }
    if (lane == 0) g_idx[n] = bi;
}

// ---------------- output + loss ----------------
__global__ void k_out(const float* __restrict__ x, float* __restrict__ out) {
    int n = blockIdx.x * 256 + threadIdx.x;
    int d = blockIdx.y;
    int idx = g_idx[n];
    float q = g_cbT[(size_t)d * KK + idx];
    size_t addr = (size_t)(n >> 11) * DD * SS + (size_t)d * SS + (n & 2047);
    float xv = x[addr];
    out[addr] = q;
    float df = q - xv;
    __shared__ float smr[256];
    smr[threadIdx.x] = df * df;
    __syncthreads();
    #pragma unroll
    for (int s2 = 128; s2 > 0; s2 >>= 1) {
        if (threadIdx.x < s2) smr[threadIdx.x] += smr[threadIdx.x + s2];
        __syncthreads();
    }
    if (threadIdx.x == 0) g_partial[blockIdx.y * gridDim.x + blockIdx.x] = smr[0];
}

__global__ void k_loss(float* __restrict__ out, int out_size) {
    __shared__ double smr[256];
    int t = threadIdx.x;
    double acc = 0.0;
    for (int j = 0; j < 256; j++) acc += (double)g_partial[t + 256 * j];
    smr[t] = acc;
    __syncthreads();
    #pragma unroll
    for (int s2 = 128; s2 > 0; s2 >>= 1) {
        if (t < s2) smr[t] += smr[t + s2];
        __syncthreads();
    }
    if (t == 0) {
        double mse = smr[0] / (double)((size_t)NN * DD);
        out[out_size - 1] = (float)(1.25 * mse);
    }
}

// ---------------- launch ----------------
extern "C" void kernel_launch(void* const* d_in, const int* in_sizes, int n_in,
                              void* d_out, int out_size) {
    const float* x  = (const float*)d_in[0];
    const float* cb = (const float*)d_in[1];
    float* out = (float*)d_out;

    static bool attr_set = false;
    if (!attr_set) {
        cudaFuncSetAttribute(k_screen, cudaFuncAttributeMaxDynamicSharedMemorySize, SM_K1_TOT);
        attr_set = true;
    }

    k_transpose<<<dim3(KK / 32, DD / 32), dim3(32, 8)>>>(cb);
    k_enorm<<<KK / 256, 256>>>(cb);
    k_rx<<<NN / 256, 256>>>(x);
    k_ebf<<<(KK * DD) / 256, 256>>>(cb);
    k_screen<<<NN / 128, 256, SM_K1_TOT>>>(x);
    k_rescue<<<NN / 8, 256>>>(x, cb);
    k_out<<<dim3(NN / 256, DD), 256>>>(x, out);
    k_loss<<<1, 256>>>(out, out_size);
}

// round 7
// speedup vs baseline: 4.3177x; 1.1104x over previous
#include <cuda_runtime.h>
#include <cuda_bf16.h>
#include <cstdint>
#include <cfloat>

#define BB 32
#define DD 256
#define SS 2048
#define NN (BB*SS)   // 65536 rows
#define KK 4096      // codes

#define MARGIN 8e-4f
#define CAP 64

// ---------------- device globals (no allocs allowed) ----------------
__device__ float g_enorm[KK];                 // ||e_k||^2
__device__ float g_rx[NN];                    // ||x_n||^2
__device__ int   g_idx[NN];                   // argmin indices
__device__ float g_partial[8192];             // loss partials
__device__ __nv_bfloat16 g_ebf[(size_t)KK*DD];   // bf16 codebook [c][d]
__device__ int   g_ccnt[NN];                  // candidate counts
__device__ int   g_cand[(size_t)NN*CAP];      // candidate code ids (16MB)

// ---------------- helpers ----------------
__device__ __forceinline__ uint32_t smem_u32(const void* p) {
    uint32_t a;
    asm("{ .reg .u64 t; cvta.to.shared.u64 t, %1; cvt.u32.u64 %0, t; }" : "=r"(a) : "l"(p));
    return a;
}
__device__ __forceinline__ void ldm_x4(uint32_t (&r)[4], uint32_t addr) {
    asm volatile("ldmatrix.sync.aligned.m8n8.x4.shared.b16 {%0,%1,%2,%3}, [%4];"
        : "=r"(r[0]), "=r"(r[1]), "=r"(r[2]), "=r"(r[3]) : "r"(addr));
}
__device__ __forceinline__ void hmma(float (&d)[4], const uint32_t (&a)[4],
                                     uint32_t b0, uint32_t b1) {
    asm volatile("mma.sync.aligned.m16n8k16.row.col.f32.bf16.bf16.f32 "
        "{%0,%1,%2,%3}, {%4,%5,%6,%7}, {%8,%9}, {%0,%1,%2,%3};"
        : "+f"(d[0]), "+f"(d[1]), "+f"(d[2]), "+f"(d[3])
        : "r"(a[0]), "r"(a[1]), "r"(a[2]), "r"(a[3]), "r"(b0), "r"(b1));
}
// monotone float<->uint encoding for atomicMin over floats
__device__ __forceinline__ unsigned fenc(float f) {
    int b = __float_as_int(f);
    return b >= 0 ? ((unsigned)b | 0x80000000u) : ~(unsigned)b;
}
__device__ __forceinline__ float fdec(unsigned u) {
    int b = (u & 0x80000000u) ? (int)(u ^ 0x80000000u) : ~(int)u;
    return __int_as_float(b);
}

// ---------------- prep kernels ----------------
__global__ void k_enorm(const float* __restrict__ cb) {
    int k = blockIdx.x * blockDim.x + threadIdx.x;
    const float* p = cb + (size_t)k * DD;
    float acc = 0.f;
    for (int d = 0; d < DD; d++) { float v = p[d]; acc = __fadd_rn(acc, __fmul_rn(v, v)); }
    g_enorm[k] = acc;
}

__global__ void k_rx(const float* __restrict__ x) {
    int n = blockIdx.x * blockDim.x + threadIdx.x;
    const float* p = x + (size_t)(n >> 11) * DD * SS + (n & 2047);
    float acc = 0.f;
    for (int d = 0; d < DD; d++) { float v = p[(size_t)d * SS]; acc = __fadd_rn(acc, __fmul_rn(v, v)); }
    g_rx[n] = acc;
    g_ccnt[n] = 0;
}

__global__ void k_ebf(const float* __restrict__ cb) {
    size_t i = (size_t)blockIdx.x * 256 + threadIdx.x;
    g_ebf[i] = __float2bfloat16(cb[i]);
}

// ---------------- K1: bf16 HMMA screen + fused candidate capture ----------
#define XH_STRIDE 264
#define E_STRIDE  40
#define SM_XH     0
#define SM_E0     67584
#define SM_E1     77824
#define SM_K1_TOT 88064

__global__ void __launch_bounds__(256, 2) k_screen(const float* __restrict__ x) {
    extern __shared__ char sm[];
    __shared__ unsigned rmin[128];     // encoded running row-min
    const uint32_t sb = smem_u32(sm);
    const int t = threadIdx.x, lane = t & 31, w = t >> 5;
    const int n0 = blockIdx.x * 128;
    const float* xbase = x + (size_t)(n0 >> 11) * DD * SS + (n0 & 2047);

    if (t < 128) rmin[t] = 0xFFFFFFFFu;

    // build Xh (bf16 rn), coalesced global reads
    for (int i = t; i < 128 * 256; i += 256) {
        int d = i >> 7, r = i & 127;
        float v = __ldg(xbase + (size_t)d * SS + r);
        *(__nv_bfloat16*)(sm + SM_XH + (r * XH_STRIDE + d) * 2) = __float2bfloat16(v);
    }

    const int wr = w & 3, wc = w >> 2;
    const int RB = wr * 32, CB = wc * 64;

    float acc[2][8][4];
    #pragma unroll
    for (int mt = 0; mt < 2; mt++)
        #pragma unroll
        for (int nt = 0; nt < 8; nt++)
            #pragma unroll
            for (int i = 0; i < 4; i++) acc[mt][nt][i] = 0.f;

    const int lc = t >> 1, lh = t & 1;
    uint4 st0, st1;
    {   // prefetch chunk 0
        const char* src = (const char*)(g_ebf + (size_t)lc * 256 + lh * 16);
        st0 = __ldg((const uint4*)src);
        st1 = __ldg((const uint4*)(src + 16));
        char* dst = sm + SM_E0 + (lc * E_STRIDE + lh * 16) * 2;
        *(uint4*)dst = st0; *(uint4*)(dst + 16) = st1;
    }
    __syncthreads();

    const int a_row = (lane & 7) + ((lane >> 3) & 1) * 8;
    const int a_kh  = ((lane >> 4) & 1) * 8;
    const int b_row = (lane & 7) + ((lane >> 4) & 1) * 8;
    const int b_kh  = ((lane >> 3) & 1) * 8;

    int cur = 0;
    for (int ci = 0; ci < 256; ci++) {       // 32 tiles x 8 k-chunks(32)
        const int tt = ci >> 3, kc = ci & 7;
        if (ci + 1 < 256) {
            int t2 = (ci + 1) >> 3, k2 = (ci + 1) & 7;
            const char* src = (const char*)(g_ebf + ((size_t)t2 * 128 + lc) * 256 + k2 * 32 + lh * 16);
            st0 = __ldg((const uint4*)src);
            st1 = __ldg((const uint4*)(src + 16));
        }
        const uint32_t ebase = sb + (cur ? SM_E1 : SM_E0);
        #pragma unroll
        for (int ks = 0; ks < 2; ks++) {
            const int k0 = kc * 32 + ks * 16;
            uint32_t a[2][4];
            #pragma unroll
            for (int mt = 0; mt < 2; mt++)
                ldm_x4(a[mt], sb + SM_XH +
                    ((RB + mt * 16 + a_row) * XH_STRIDE + k0 + a_kh) * 2);
            uint32_t bf[4][4];
            #pragma unroll
            for (int p = 0; p < 4; p++)
                ldm_x4(bf[p], ebase +
                    ((CB + p * 16 + b_row) * E_STRIDE + ks * 16 + b_kh) * 2);
            #pragma unroll
            for (int mt = 0; mt < 2; mt++)
                #pragma unroll
                for (int nt = 0; nt < 8; nt++)
                    hmma(acc[mt][nt], a[mt], bf[nt >> 1][(nt & 1) * 2],
                         bf[nt >> 1][(nt & 1) * 2 + 1]);
        }
        if (ci + 1 < 256) {
            char* dst = sm + (cur ? SM_E0 : SM_E1) + (lc * E_STRIDE + lh * 16) * 2;
            *(uint4*)dst = st0; *(uint4*)(dst + 16) = st1;
        }
        // tile epilogue: running row-min update + capture, NO extra syncs.
        // rmin only decreases; an unsynced read is >= final min, so the
        // captured set is a superset of the true margin set (rescue exact).
        if (kc == 7) {
            const int tb = tt * 128;
            #pragma unroll
            for (int mt = 0; mt < 2; mt++) {
                float mn01 = FLT_MAX, mn23 = FLT_MAX;
                #pragma unroll
                for (int nt = 0; nt < 8; nt++) {
                    const int gcol = tb + CB + nt * 8 + (lane & 3) * 2;
                    float2 ce = __ldg((const float2*)&g_enorm[gcol]);
                    mn01 = fminf(mn01, fminf(ce.x - 2.f * acc[mt][nt][0],
                                             ce.y - 2.f * acc[mt][nt][1]));
                    mn23 = fminf(mn23, fminf(ce.x - 2.f * acc[mt][nt][2],
                                             ce.y - 2.f * acc[mt][nt][3]));
                }
                const int r0 = RB + mt * 16 + (lane >> 2);
                atomicMin(&rmin[r0], fenc(mn01));
                atomicMin(&rmin[r0 + 8], fenc(mn23));
            }
            #pragma unroll
            for (int mt = 0; mt < 2; mt++) {
                const int r0 = RB + mt * 16 + (lane >> 2);
                const float th0 = fdec(rmin[r0]) + MARGIN;
                const float th1 = fdec(rmin[r0 + 8]) + MARGIN;
                #pragma unroll
                for (int nt = 0; nt < 8; nt++) {
                    const int gcol = tb + CB + nt * 8 + (lane & 3) * 2;
                    float2 ce = __ldg((const float2*)&g_enorm[gcol]);
                    float s0 = ce.x - 2.f * acc[mt][nt][0];
                    float s1 = ce.y - 2.f * acc[mt][nt][1];
                    float s2 = ce.x - 2.f * acc[mt][nt][2];
                    float s3 = ce.y - 2.f * acc[mt][nt][3];
                    if (s0 <= th0) {
                        int p = atomicAdd(&g_ccnt[n0 + r0], 1);
                        if (p < CAP) g_cand[(size_t)(n0 + r0) * CAP + p] = gcol;
                    }
                    if (s1 <= th0) {
                        int p = atomicAdd(&g_ccnt[n0 + r0], 1);
                        if (p < CAP) g_cand[(size_t)(n0 + r0) * CAP + p] = gcol + 1;
                    }
                    if (s2 <= th1) {
                        int p = atomicAdd(&g_ccnt[n0 + r0 + 8], 1);
                        if (p < CAP) g_cand[(size_t)(n0 + r0 + 8) * CAP + p] = gcol;
                    }
                    if (s3 <= th1) {
                        int p = atomicAdd(&g_ccnt[n0 + r0 + 8], 1);
                        if (p < CAP) g_cand[(size_t)(n0 + r0 + 8) * CAP + p] = gcol + 1;
                    }
                    acc[mt][nt][0] = acc[mt][nt][1] = acc[mt][nt][2] = acc[mt][nt][3] = 0.f;
                }
            }
        }
        __syncthreads();
        cur ^= 1;
    }
}

// ---------------- K2: exact rescue over candidates (warp per row) --------
__global__ void __launch_bounds__(256) k_rescue(const float* __restrict__ x,
                                                const float* __restrict__ cb) {
    const int n = (blockIdx.x * 256 + threadIdx.x) >> 5;
    const int lane = threadIdx.x & 31;
    const float* xp = x + (size_t)(n >> 11) * DD * SS + (n & 2047);

    float xr[8];
    #pragma unroll
    for (int j = 0; j < 8; j++)
        xr[j] = __ldg(xp + (size_t)(lane + 32 * j) * SS);

    int cnt = __ldg(&g_ccnt[n]);
    if (cnt > CAP) cnt = CAP;
    const float rxv = __ldg(&g_rx[n]);

    float bd = FLT_MAX; int bi = 0x7fffffff;
    for (int i = 0; i < cnt; i++) {
        int c = __ldg(&g_cand[(size_t)n * CAP + i]);
        const float* ep = cb + (size_t)c * DD;
        float pa = 0.f;
        #pragma unroll
        for (int j = 0; j < 8; j++)
            pa = fmaf(xr[j], __ldg(ep + lane + 32 * j), pa);
        #pragma unroll
        for (int o = 16; o > 0; o >>= 1)
            pa += __shfl_down_sync(0xFFFFFFFFu, pa, o);
        pa = __shfl_sync(0xFFFFFFFFu, pa, 0);
        float ce = __ldg(&g_enorm[c]);
        float dist = __fsub_rn(__fadd_rn(rxv, ce), __fmul_rn(2.0f, pa));
        if (dist < bd || (dist == bd && c < bi)) { bd = dist; bi = c; }
    }
    if (lane == 0) g_idx[n] = bi;
}

// ---------------- output + loss (8 d per thread, sector-dense gather) -----
__global__ void k_out(const float* __restrict__ x, const float* __restrict__ cb,
                      float* __restrict__ out) {
    int n = blockIdx.x * 256 + threadIdx.x;
    int d0 = blockIdx.y * 8;
    int idx = __ldg(&g_idx[n]);
    float4 q0 = __ldg((const float4*)(cb + (size_t)idx * DD + d0));
    float4 q1 = __ldg((const float4*)(cb + (size_t)idx * DD + d0 + 4));
    float q[8] = {q0.x, q0.y, q0.z, q0.w, q1.x, q1.y, q1.z, q1.w};

    size_t base = (size_t)(n >> 11) * DD * SS + (size_t)d0 * SS + (n & 2047);
    float sq = 0.f;
    #pragma unroll
    for (int dd = 0; dd < 8; dd++) {
        size_t addr = base + (size_t)dd * SS;
        float xv = __ldg(&x[addr]);
        out[addr] = q[dd];
        float df = q[dd] - xv;
        sq += df * df;
    }

    __shared__ float smr[256];
    smr[threadIdx.x] = sq;
    __syncthreads();
    #pragma unroll
    for (int s2 = 128; s2 > 0; s2 >>= 1) {
        if (threadIdx.x < s2) smr[threadIdx.x] += smr[threadIdx.x + s2];
        __syncthreads();
    }
    if (threadIdx.x == 0)
        g_partial[blockIdx.y * gridDim.x + blockIdx.x] = smr[0];
}

__global__ void k_loss(float* __restrict__ out, int out_size) {
    __shared__ double smr[256];
    int t = threadIdx.x;
    double acc = 0.0;
    for (int j = 0; j < 32; j++)
        acc += (double)g_partial[t + 256 * j];
    smr[t] = acc;
    __syncthreads();
    #pragma unroll
    for (int s2 = 128; s2 > 0; s2 >>= 1) {
        if (t < s2) smr[t] += smr[t + s2];
        __syncthreads();
    }
    if (t == 0) {
        double mse = smr[0] / (double)((size_t)NN * DD);
        out[out_size - 1] = (float)(1.25 * mse);
    }
}

// ---------------- launch ----------------
extern "C" void kernel_launch(void* const* d_in, const int* in_sizes, int n_in,
                              void* d_out, int out_size) {
    const float* x  = (const float*)d_in[0];
    const float* cb = (const float*)d_in[1];
    float* out = (float*)d_out;

    static bool attr_set = false;
    if (!attr_set) {
        cudaFuncSetAttribute(k_screen, cudaFuncAttributeMaxDynamicSharedMemorySize, SM_K1_TOT);
        attr_set = true;
    }

    k_enorm<<<KK / 256, 256>>>(cb);
    k_rx<<<NN / 256, 256>>>(x);
    k_ebf<<<(KK * DD) / 256, 256>>>(cb);
    k_screen<<<NN / 128, 256, SM_K1_TOT>>>(x);
    k_rescue<<<NN / 8, 256>>>(x, cb);
    k_out<<<dim3(NN / 256, DD / 8), 256>>>(x, cb, out);
    k_loss<<<1, 256>>>(out, out_size);
}